// round 8
// baseline (speedup 1.0000x reference)
#include <cuda_runtime.h>

#define HW  2304              // 48*48
#define HW2 1152              // HW/2 (float2 plane stride)
#define NIMG 128              // B*N
#define PRED_I_ELEMS 884736   // 16*8*3*48*48
#define PRED_ELEMS   110592   // 16*3*48*48
#define CHUNKS 12             // row-chunks per image (4 rows each)
#define BLK_PER_B (8 * CHUNKS) // blocks per batch index b

__device__ float g_pred_i_scratch[PRED_I_ELEMS];
// Monotonic completion counters, one per b. Never reset: each launch adds
// exactly BLK_PER_B per counter, so ((old+1) % BLK_PER_B)==0 marks the last block.
__device__ unsigned int g_done_cnt[16];

// grid = 1536: blockIdx.x -> (bn = bx/12, chunk = bx%12). Block = 4 rows.
// 96 threads; each thread owns a 2-pixel pair (float2). Warp LDG.64 = 256B coalesced.
__global__ __launch_bounds__(96, 7)
void conv_fused_kernel(const float* __restrict__ frames,
                       const float* __restrict__ core,
                       const float* __restrict__ kwt,
                       float* __restrict__ pred_i,
                       float* __restrict__ pred) {     // may be nullptr
    const int bn = blockIdx.x / CHUNKS;
    const int r0 = (blockIdx.x % CHUNKS) * 4;          // first pixel row

    // channel-summed zero-padded frame tile for rows [r0-2, r0+5]: 8x52 floats
    __shared__ float fsum[8 * 52];
    {
        const float* fr = frames + (size_t)bn * 3 * HW;
        for (int i = threadIdx.x; i < 8 * 52; i += 96) {
            int yy = r0 - 2 + i / 52;
            int xx = i % 52 - 2;
            float v = 0.f;
            if ((unsigned)yy < 48u && (unsigned)xx < 48u) {
                int p = yy * 48 + xx;
                v = fr[p] + fr[HW + p] + fr[2 * HW + p];
            }
            fsum[i] = v;
        }
    }
    __syncthreads();

    const float* cb = core + (size_t)bn * 300 * HW;   // [300,H,W] planes
    const float* kb = kwt  + (size_t)bn * 12  * HW;   // [4,3,H,W] planes
    float*       ob = pred_i + (size_t)bn * 3 * HW;

    const int xp = threadIdx.x % 24;                  // float2 index in row
    const int yl = threadIdx.x / 24;                  // 0..3
    const int y  = r0 + yl;
    const int pix2 = y * 24 + xp;                     // float2 index (8B aligned)

    // 5x6 window of shifted frame-sums covering this thread's 2 pixels
    float win[5][6];
    #pragma unroll
    for (int i = 0; i < 5; ++i)
        #pragma unroll
        for (int j = 0; j < 6; ++j)
            win[i][j] = fsum[(yl + i) * 52 + xp * 2 + j];

    float2 a0 = {0,0}, a1 = {0,0}, a2 = {0,0};

    #pragma unroll
    for (int g = 0; g < 4; ++g) {
        // pk[g,k,c] lives at core mid-index m = g*75 + 3k + c
        const float2* cg = (const float2*)(cb + (size_t)(g * 75) * HW) + pix2;
        float2 s0 = {0,0}, s1 = {0,0}, s2 = {0,0};
        #pragma unroll
        for (int k = 0; k < 25; ++k) {
            const int i = k / 5, j = k % 5;
            const float2 c0 = __ldcs(&cg[(3 * k + 0) * HW2]);
            const float2 c1 = __ldcs(&cg[(3 * k + 1) * HW2]);
            const float2 c2 = __ldcs(&cg[(3 * k + 2) * HW2]);
            const float f0 = win[i][j], f1 = win[i][j + 1];
            s0.x = fmaf(f0, c0.x, s0.x);  s0.y = fmaf(f1, c0.y, s0.y);
            s1.x = fmaf(f0, c1.x, s1.x);  s1.y = fmaf(f1, c1.y, s1.y);
            s2.x = fmaf(f0, c2.x, s2.x);  s2.y = fmaf(f1, c2.y, s2.y);
        }
        const float2* kg = (const float2*)kb + pix2;
        const float2 w0 = __ldcs(&kg[(g * 3 + 0) * HW2]);
        const float2 w1 = __ldcs(&kg[(g * 3 + 1) * HW2]);
        const float2 w2 = __ldcs(&kg[(g * 3 + 2) * HW2]);
        a0.x = fmaf(w0.x, s0.x, a0.x);  a0.y = fmaf(w0.y, s0.y, a0.y);
        a1.x = fmaf(w1.x, s1.x, a1.x);  a1.y = fmaf(w1.y, s1.y, a1.y);
        a2.x = fmaf(w2.x, s2.x, a2.x);  a2.y = fmaf(w2.y, s2.y, a2.y);
    }

    float2* o2 = (float2*)ob + pix2;
    o2[0]       = make_float2(0.25f * a0.x, 0.25f * a0.y);
    o2[HW2]     = make_float2(0.25f * a1.x, 0.25f * a1.y);
    o2[2 * HW2] = make_float2(0.25f * a2.x, 0.25f * a2.y);

    if (pred == nullptr) return;

    // ---- fused mean-over-n: last finished block of each b does the reduce ----
    const int b = bn >> 3;                   // 8 n per b, CHUNKS blocks per (b,n)
    __shared__ unsigned int s_last;
    __threadfence();                         // publish pred_i writes
    __syncthreads();
    if (threadIdx.x == 0) {
        unsigned int old = atomicAdd(&g_done_cnt[b], 1u);
        s_last = (((old + 1u) % BLK_PER_B) == 0u);
    }
    __syncthreads();
    if (!s_last) return;
    __threadfence();                         // acquire: see peers' pred_i writes

    const int perb4 = 3 * HW / 4;            // 1728 float4 per (c,h,w) slab
    const float4* pbase = (const float4*)pred_i + (size_t)b * 8 * perb4;
    float4* pout = (float4*)pred + (size_t)b * perb4;
    for (int r = threadIdx.x; r < perb4; r += 96) {
        float4 s = {0,0,0,0};
        #pragma unroll
        for (int n = 0; n < 8; ++n) {
            float4 v = pbase[(size_t)n * perb4 + r];
            s.x += v.x; s.y += v.y; s.z += v.z; s.w += v.w;
        }
        s.x *= 0.125f; s.y *= 0.125f; s.z *= 0.125f; s.w *= 0.125f;
        pout[r] = s;
    }
}

extern "C" void kernel_launch(void* const* d_in, const int* in_sizes, int n_in,
                              void* d_out, int out_size) {
    const float* frames = (const float*)d_in[0];
    const float* core   = (const float*)d_in[1];
    const float* kwt    = (const float*)d_in[2];
    float* out = (float*)d_out;
    const int grid = NIMG * CHUNKS;

    if (out_size >= PRED_I_ELEMS + PRED_ELEMS) {
        conv_fused_kernel<<<grid, 96>>>(frames, core, kwt, out, out + PRED_I_ELEMS);
    } else if (out_size >= PRED_I_ELEMS) {
        conv_fused_kernel<<<grid, 96>>>(frames, core, kwt, out, nullptr);
    } else {
        conv_fused_kernel<<<grid, 96>>>(frames, core, kwt, g_pred_i_scratch, out);
    }
}

// round 10
// speedup vs baseline: 1.0686x; 1.0686x over previous
#include <cuda_runtime.h>
#include <cstdint>

#define HW 2304               // 48*48
#define HW4 576               // HW/4 (float4 plane stride)
#define NIMG 128              // B*N
#define PRED_I_ELEMS 884736   // 16*8*3*48*48
#define PRED_ELEMS   110592   // 16*3*48*48
#define CHUNKS 3              // 16-row chunks per image
#define BLK_PER_B (8 * CHUNKS)
#define STAGES 4
#define THREADS 192

__device__ float g_pred_i_scratch[PRED_I_ELEMS];
// Monotonic completion counters, one per b. Never reset: each launch adds
// exactly BLK_PER_B per counter, so ((old+1) % BLK_PER_B)==0 marks the last block.
__device__ unsigned int g_done_cnt[16];

__device__ __forceinline__ void cp16(uint32_t dst, const float* src) {
    asm volatile("cp.async.cg.shared.global [%0], [%1], 16;\n"
                 :: "r"(dst), "l"(src) : "memory");
}
__device__ __forceinline__ void cp_commit() {
    asm volatile("cp.async.commit_group;\n" ::: "memory");
}
__device__ __forceinline__ void cp_wait() {
    asm volatile("cp.async.wait_group %0;\n" :: "n"(STAGES - 1) : "memory");
}

// grid = 384: blockIdx.x -> (bn = bx/3, chunk = bx%3). Block = 16 rows.
// 192 threads; thread owns one 4-pixel quad; quad offset within chunk = 4*tid,
// so the cp.async staging layout ring[stage][c][tid] is copy- and LDS-conflict-free.
__global__ __launch_bounds__(THREADS, 3)
void conv_fused_kernel(const float* __restrict__ frames,
                       const float* __restrict__ core,
                       const float* __restrict__ kwt,
                       float* __restrict__ pred_i,
                       float* __restrict__ pred) {     // may be nullptr
    const int tid = threadIdx.x;
    const int bn  = blockIdx.x / CHUNKS;
    const int r0  = (blockIdx.x % CHUNKS) * 16;

    __shared__ float4 ring[STAGES][3][THREADS];        // 36864 B
    __shared__ float fsum[20 * 52];                    // rows r0-2 .. r0+17

    const float* cb = core + (size_t)bn * 300 * HW;    // [300,H,W] planes
    const float* kb = kwt  + (size_t)bn * 12  * HW;
    float*       ob = pred_i + (size_t)bn * 3 * HW;

    const int xb   = (tid % 12) * 4;
    const int yl   = tid / 12;                         // 0..15
    const int pixq = (r0 + yl) * 48 + xb;              // 16B-aligned quad start

    const uint32_t rbase = (uint32_t)__cvta_generic_to_shared(ring);
    // ring slot address for (stage s, channel c): rbase + ((s*3+c)*THREADS + tid)*16
    const uint32_t roff = tid * 16u;

    // ---- prologue: issue stages 0..3 (planes m = 3t + c, pure sequential) ----
    const float* src = cb + pixq;                      // plane 0 at this quad
    #pragma unroll
    for (int t = 0; t < STAGES; ++t) {
        #pragma unroll
        for (int c = 0; c < 3; ++c)
            cp16(rbase + (uint32_t)((t * 3 + c) * THREADS) * 16u + roff,
                 src + (size_t)(3 * t + c) * HW);
        cp_commit();
    }
    const float* src_next = cb + (size_t)(3 * STAGES) * HW + pixq;

    // ---- channel-summed zero-padded frame tile (overlaps with cp.async) ----
    {
        const float* fr = frames + (size_t)bn * 3 * HW;
        for (int i = tid; i < 20 * 52; i += THREADS) {
            int yy = r0 - 2 + i / 52;
            int xx = i % 52 - 2;
            float v = 0.f;
            if ((unsigned)yy < 48u && (unsigned)xx < 48u) {
                int p = yy * 48 + xx;
                v = fr[p] + fr[HW + p] + fr[2 * HW + p];
            }
            fsum[i] = v;
        }
    }
    __syncthreads();

    // 5x8 window of shifted frame-sums for this thread's 4 pixels
    float win[5][8];
    #pragma unroll
    for (int i = 0; i < 5; ++i)
        #pragma unroll
        for (int j = 0; j < 8; ++j)
            win[i][j] = fsum[(yl + i) * 52 + xb + j];

    float4 a0 = {0,0,0,0}, a1 = {0,0,0,0}, a2 = {0,0,0,0};
    int slot = 0;

    #pragma unroll 1
    for (int g = 0; g < 4; ++g) {
        // prefetch this g's kernel weights now; consumed ~25 steps later
        const float4* kg = (const float4*)(kb + pixq);
        const float4 w0 = kg[(g * 3 + 0) * HW4];
        const float4 w1 = kg[(g * 3 + 1) * HW4];
        const float4 w2 = kg[(g * 3 + 2) * HW4];

        float4 s0 = {0,0,0,0}, s1 = {0,0,0,0}, s2 = {0,0,0,0};
        #pragma unroll
        for (int k = 0; k < 25; ++k) {
            const int i = k / 5, j = k % 5;
            cp_wait();                                  // oldest stage resident
            const float4 c0 = ring[slot][0][tid];
            const float4 c1 = ring[slot][1][tid];
            const float4 c2 = ring[slot][2][tid];
            // refill this slot with step t+STAGES (uniform branch)
            if (g * 25 + k + STAGES < 100) {
                #pragma unroll
                for (int c = 0; c < 3; ++c)
                    cp16(rbase + (uint32_t)((slot * 3 + c) * THREADS) * 16u + roff,
                         src_next + (size_t)c * HW);
            }
            cp_commit();                                // may be an empty group
            src_next += (size_t)3 * HW;
            slot = (slot + 1) & (STAGES - 1);

            const float f0 = win[i][j + 0], f1 = win[i][j + 1];
            const float f2 = win[i][j + 2], f3 = win[i][j + 3];
            s0.x = fmaf(f0, c0.x, s0.x); s0.y = fmaf(f1, c0.y, s0.y);
            s0.z = fmaf(f2, c0.z, s0.z); s0.w = fmaf(f3, c0.w, s0.w);
            s1.x = fmaf(f0, c1.x, s1.x); s1.y = fmaf(f1, c1.y, s1.y);
            s1.z = fmaf(f2, c1.z, s1.z); s1.w = fmaf(f3, c1.w, s1.w);
            s2.x = fmaf(f0, c2.x, s2.x); s2.y = fmaf(f1, c2.y, s2.y);
            s2.z = fmaf(f2, c2.z, s2.z); s2.w = fmaf(f3, c2.w, s2.w);
        }
        a0.x = fmaf(w0.x, s0.x, a0.x); a0.y = fmaf(w0.y, s0.y, a0.y);
        a0.z = fmaf(w0.z, s0.z, a0.z); a0.w = fmaf(w0.w, s0.w, a0.w);
        a1.x = fmaf(w1.x, s1.x, a1.x); a1.y = fmaf(w1.y, s1.y, a1.y);
        a1.z = fmaf(w1.z, s1.z, a1.z); a1.w = fmaf(w1.w, s1.w, a1.w);
        a2.x = fmaf(w2.x, s2.x, a2.x); a2.y = fmaf(w2.y, s2.y, a2.y);
        a2.z = fmaf(w2.z, s2.z, a2.z); a2.w = fmaf(w2.w, s2.w, a2.w);
    }

    float4* o4 = (float4*)(ob + pixq);
    o4[0]       = make_float4(0.25f*a0.x, 0.25f*a0.y, 0.25f*a0.z, 0.25f*a0.w);
    o4[HW4]     = make_float4(0.25f*a1.x, 0.25f*a1.y, 0.25f*a1.z, 0.25f*a1.w);
    o4[2 * HW4] = make_float4(0.25f*a2.x, 0.25f*a2.y, 0.25f*a2.z, 0.25f*a2.w);

    if (pred == nullptr) return;

    // ---- fused mean-over-n: last finished block of each b does the reduce ----
    const int b = bn >> 3;
    __shared__ unsigned int s_last;
    __threadfence();                         // publish pred_i writes
    __syncthreads();
    if (tid == 0) {
        unsigned int old = atomicAdd(&g_done_cnt[b], 1u);
        s_last = (((old + 1u) % BLK_PER_B) == 0u);
    }
    __syncthreads();
    if (!s_last) return;
    __threadfence();                         // acquire: see peers' pred_i writes

    const int perb4 = 3 * HW / 4;            // 1728 float4 per (c,h,w) slab
    const float4* pbase = (const float4*)pred_i + (size_t)b * 8 * perb4;
    float4* pout = (float4*)pred + (size_t)b * perb4;
    for (int r = tid; r < perb4; r += THREADS) {
        float4 s = {0,0,0,0};
        #pragma unroll
        for (int n = 0; n < 8; ++n) {
            float4 v = pbase[(size_t)n * perb4 + r];
            s.x += v.x; s.y += v.y; s.z += v.z; s.w += v.w;
        }
        s.x *= 0.125f; s.y *= 0.125f; s.z *= 0.125f; s.w *= 0.125f;
        pout[r] = s;
    }
}

extern "C" void kernel_launch(void* const* d_in, const int* in_sizes, int n_in,
                              void* d_out, int out_size) {
    const float* frames = (const float*)d_in[0];
    const float* core   = (const float*)d_in[1];
    const float* kwt    = (const float*)d_in[2];
    float* out = (float*)d_out;
    const int grid = NIMG * CHUNKS;

    if (out_size >= PRED_I_ELEMS + PRED_ELEMS) {
        conv_fused_kernel<<<grid, THREADS>>>(frames, core, kwt,
                                             out, out + PRED_I_ELEMS);
    } else if (out_size >= PRED_I_ELEMS) {
        conv_fused_kernel<<<grid, THREADS>>>(frames, core, kwt, out, nullptr);
    } else {
        conv_fused_kernel<<<grid, THREADS>>>(frames, core, kwt,
                                             g_pred_i_scratch, out);
    }
}

// round 11
// speedup vs baseline: 1.1170x; 1.0453x over previous
#include <cuda_runtime.h>

#define HW 2304               // 48*48
#define HW4 576               // HW/4 (float4 plane stride)
#define NIMG 128              // B*N
#define PRED_I_ELEMS 884736   // 16*8*3*48*48
#define PRED_ELEMS   110592   // 16*3*48*48

__device__ float g_pred_i_scratch[PRED_I_ELEMS];

// One block per (b,n) image; exactly 1 CTA/SM (no cross-CTA L1tex contention).
// 576 threads = 48 rows x 12 quads; each thread owns one 4-pixel float4 quad.
__global__ __launch_bounds__(576, 1)
void conv_fused_kernel(const float* __restrict__ frames,
                       const float* __restrict__ core,
                       const float* __restrict__ kwt,
                       float* __restrict__ out_pred_i) {
    const int bn  = blockIdx.x;
    const int tid = threadIdx.x;

    // channel-summed, zero-padded frame tile: fsum[(y+2)*52 + (x+2)]
    __shared__ float fsum[52 * 52];
    {
        const float* fr = frames + (size_t)bn * 3 * HW;
        for (int i = tid; i < 52 * 52; i += 576) {
            int yy = i / 52 - 2;
            int xx = i % 52 - 2;
            float v = 0.f;
            if ((unsigned)yy < 48u && (unsigned)xx < 48u) {
                int p = yy * 48 + xx;
                v = fr[p] + fr[HW + p] + fr[2 * HW + p];
            }
            fsum[i] = v;
        }
    }
    __syncthreads();

    const float* cb = core + (size_t)bn * 300 * HW;  // [300,H,W] planes
    const float* kb = kwt  + (size_t)bn * 12  * HW;  // [4,3,H,W] planes
    float*       ob = out_pred_i + (size_t)bn * 3 * HW;

    const int xb   = (tid % 12) * 4;
    const int y    = tid / 12;                       // 0..47
    const int pixq = y * 48 + xb;                    // 16B-aligned quad start

    // 5x8 window of shifted frame-sums covering this thread's 4 pixels
    float win[5][8];
    #pragma unroll
    for (int i = 0; i < 5; ++i)
        #pragma unroll
        for (int j = 0; j < 8; ++j)
            win[i][j] = fsum[(y + i) * 52 + xb + j];

    float4 a0 = {0,0,0,0}, a1 = {0,0,0,0}, a2 = {0,0,0,0};

    #pragma unroll
    for (int g = 0; g < 4; ++g) {
        // pk[g,k,c] lives at core mid-index m = g*75 + 3k + c
        const float4* cg = (const float4*)(cb + (size_t)(g * 75) * HW + pixq);
        float4 s0 = {0,0,0,0}, s1 = {0,0,0,0}, s2 = {0,0,0,0};
        #pragma unroll
        for (int k = 0; k < 25; ++k) {
            const int i = k / 5, j = k % 5;
            const float4 c0 = cg[(3 * k + 0) * HW4];
            const float4 c1 = cg[(3 * k + 1) * HW4];
            const float4 c2 = cg[(3 * k + 2) * HW4];
            s0.x = fmaf(win[i][j+0], c0.x, s0.x);
            s0.y = fmaf(win[i][j+1], c0.y, s0.y);
            s0.z = fmaf(win[i][j+2], c0.z, s0.z);
            s0.w = fmaf(win[i][j+3], c0.w, s0.w);
            s1.x = fmaf(win[i][j+0], c1.x, s1.x);
            s1.y = fmaf(win[i][j+1], c1.y, s1.y);
            s1.z = fmaf(win[i][j+2], c1.z, s1.z);
            s1.w = fmaf(win[i][j+3], c1.w, s1.w);
            s2.x = fmaf(win[i][j+0], c2.x, s2.x);
            s2.y = fmaf(win[i][j+1], c2.y, s2.y);
            s2.z = fmaf(win[i][j+2], c2.z, s2.z);
            s2.w = fmaf(win[i][j+3], c2.w, s2.w);
        }
        const float4* kg = (const float4*)(kb + pixq);
        const float4 w0 = kg[(g * 3 + 0) * HW4];
        const float4 w1 = kg[(g * 3 + 1) * HW4];
        const float4 w2 = kg[(g * 3 + 2) * HW4];
        a0.x = fmaf(w0.x, s0.x, a0.x); a0.y = fmaf(w0.y, s0.y, a0.y);
        a0.z = fmaf(w0.z, s0.z, a0.z); a0.w = fmaf(w0.w, s0.w, a0.w);
        a1.x = fmaf(w1.x, s1.x, a1.x); a1.y = fmaf(w1.y, s1.y, a1.y);
        a1.z = fmaf(w1.z, s1.z, a1.z); a1.w = fmaf(w1.w, s1.w, a1.w);
        a2.x = fmaf(w2.x, s2.x, a2.x); a2.y = fmaf(w2.y, s2.y, a2.y);
        a2.z = fmaf(w2.z, s2.z, a2.z); a2.w = fmaf(w2.w, s2.w, a2.w);
    }

    float4* o4 = (float4*)(ob + pixq);
    o4[0]       = make_float4(0.25f*a0.x, 0.25f*a0.y, 0.25f*a0.z, 0.25f*a0.w);
    o4[HW4]     = make_float4(0.25f*a1.x, 0.25f*a1.y, 0.25f*a1.z, 0.25f*a1.w);
    o4[2 * HW4] = make_float4(0.25f*a2.x, 0.25f*a2.y, 0.25f*a2.z, 0.25f*a2.w);
}

// pred_img = mean over n of pred_img_i. 27648 float4 outputs; pred_i is
// freshly written -> L2-resident, so use __ldcg and lots of small blocks.
__global__ __launch_bounds__(128)
void mean_over_n_kernel(const float* __restrict__ pred_i,
                        float* __restrict__ pred) {
    const int nq = PRED_ELEMS / 4;            // 27648 quads
    int idx = blockIdx.x * blockDim.x + threadIdx.x;
    if (idx >= nq) return;
    const int perb = 3 * HW4;                 // 1728 quads per (c,h,w) slab
    int b = idx / perb;
    int r = idx - b * perb;
    const float4* p = (const float4*)pred_i + (size_t)b * 8 * perb + r;
    float4 s = {0,0,0,0};
    #pragma unroll
    for (int n = 0; n < 8; ++n) {
        float4 v = __ldcg(&p[(size_t)n * perb]);
        s.x += v.x; s.y += v.y; s.z += v.z; s.w += v.w;
    }
    s.x *= 0.125f; s.y *= 0.125f; s.z *= 0.125f; s.w *= 0.125f;
    ((float4*)pred)[idx] = s;
}

extern "C" void kernel_launch(void* const* d_in, const int* in_sizes, int n_in,
                              void* d_out, int out_size) {
    const float* frames = (const float*)d_in[0];
    const float* core   = (const float*)d_in[1];
    const float* kwt    = (const float*)d_in[2];
    float* out = (float*)d_out;

    const int mean_blocks = (PRED_ELEMS / 4 + 127) / 128;   // 216

    if (out_size >= PRED_I_ELEMS + PRED_ELEMS) {
        conv_fused_kernel<<<NIMG, 576>>>(frames, core, kwt, out);
        mean_over_n_kernel<<<mean_blocks, 128>>>(out, out + PRED_I_ELEMS);
    } else if (out_size >= PRED_I_ELEMS) {
        conv_fused_kernel<<<NIMG, 576>>>(frames, core, kwt, out);
    } else {
        conv_fused_kernel<<<NIMG, 576>>>(frames, core, kwt, g_pred_i_scratch);
        mean_over_n_kernel<<<mean_blocks, 128>>>(g_pred_i_scratch, out);
    }
}